// round 5
// baseline (speedup 1.0000x reference)
#include <cuda_runtime.h>
#include <stdint.h>

// ============================================================================
// Fused colorization L2Loss, one kernel, occupancy-safe grid barrier.
//   loss = mean_b sum_{c,h,w} (in-tgt)^2 * prior[argmin_q d2(tgt_px, gamut[q])]
//
// Phase 1 (build): one warp per 64x64 cell (grid-stride). Candidate set =
//   bins with d(center,bin) <= dmin(center)+diag  (provable NN superset).
//   Writes 8 MATERIALIZED candidates per cell: float4(-2gx,-2gy,|g|^2+16,prior),
//   dup-padded. Flags: slot0.z<0 => >4 candidates; slot4.z<0 => >8 (full scan).
// Barrier: grid sized to SMs x maxActiveBlocks => all blocks co-resident by
//   construction. atomicAdd arrive + volatile-load poll.
// Phase 2 (loss): 1 px/thread grid-stride; 4 parallel LDG.128 candidate loads,
//   weight selected alongside score (no index, no shared). Block reduce+atomic.
// ============================================================================

#define LGRID 64
#define NCELL (LGRID * LGRID)
#define MAXQ  512
#define NTHR  256

__device__ float4 g_tab[NCELL * 8];          // 512 KB candidate table
__device__ volatile unsigned int g_arrive;   // zero-init; reset at end
__device__ unsigned int          g_done;

__global__ void __launch_bounds__(NTHR) fused_loss_kernel(
    const float*  __restrict__ input,
    const float*  __restrict__ target,
    const float2* __restrict__ gamut,
    const float*  __restrict__ prior,
    float*        __restrict__ out,
    int Q, int nblk)
{
    __shared__ float4 sf[MAXQ];              // (-2gx, -2gy, |g|^2+16, prior)
    __shared__ unsigned short scand[8][32];
    __shared__ float ws[8];

    for (int i = threadIdx.x; i < Q; i += NTHR) {
        const float2 g = gamut[i];
        sf[i] = make_float4(-2.0f * g.x, -2.0f * g.y,
                            fmaf(g.x, g.x, fmaf(g.y, g.y, 16.0f)),
                            prior[i]);
    }
    __syncthreads();

    const int warp = threadIdx.x >> 5;
    const int lane = threadIdx.x & 31;
    const int gwarp  = blockIdx.x * 8 + warp;
    const int nwarps = nblk * 8;
    const int nIter  = (Q + 31) >> 5;

    // ---------------- Phase 1: build table (one warp per cell) --------------
    for (int cell = gwarp; cell < NCELL; cell += nwarps) {
        const int ix = cell & (LGRID - 1);
        const int iy = cell >> 6;
        const float cellw = 2.0f / (float)LGRID;
        const float cx = -1.0f + ((float)ix + 0.5f) * cellw;
        const float cy = -1.0f + ((float)iy + 0.5f) * cellw;
        const float c2 = fmaf(cx, cx, cy * cy);
        const float diag = 0.04450f;          // cell diagonal 0.044194 + pad

        // score = d2 + 16 - c2, same fma form as phase 2
        float scv[(MAXQ + 31) / 32];
        float smin = 1e30f;
        #pragma unroll
        for (int j = 0; j < (MAXQ + 31) / 32; j++) {
            if (j >= nIter) break;
            const int b = (j << 5) + lane;
            float sc = 1e30f;
            if (b < Q) {
                const float4 g = sf[b];
                sc = fmaf(g.x, cx, fmaf(g.y, cy, g.z));
            }
            scv[j] = sc;
            smin = fminf(smin, sc);
        }
        #pragma unroll
        for (int off = 16; off; off >>= 1)
            smin = fminf(smin, __shfl_xor_sync(0xFFFFFFFFu, smin, off));

        const float d2min = fmaxf(smin - 16.0f + c2, 0.0f);
        const float s     = sqrtf(d2min) + diag;
        const float thr   = fmaf(s, s, 16.0f - c2) + 2e-5f;

        int base = 0;
        for (int j = 0; j < nIter; j++) {
            const bool take = (scv[j] <= thr);
            const unsigned m = __ballot_sync(0xFFFFFFFFu, take);
            if (take) {
                const int pos = base + __popc(m & ((1u << lane) - 1u));
                if (pos < 32)
                    scand[warp][pos] = (unsigned short)((j << 5) + lane);
            }
            base += __popc(m);
        }
        __syncwarp();

        // lanes 0..7 write the 8 materialized slots (ascending index order,
        // dup-padded with slot0; overflow flags in sign of z)
        if (lane < 8) {
            const int cnt = base;                       // >= 1 always
            const int sel = (lane < cnt) ? lane : 0;
            float4 v = sf[scand[warp][sel]];
            if (lane == 0 && cnt > 4) v.z = -v.z;
            if (lane == 4 && cnt > 8) v.z = -v.z;
            g_tab[cell * 8 + lane] = v;
        }
        __syncwarp();
    }

    if (blockIdx.x == 0 && threadIdx.x == 0) out[0] = 0.0f;

    // -------- Grid barrier (co-residency guaranteed by host grid sizing) ----
    __syncthreads();
    if (threadIdx.x == 0) {
        __threadfence();                     // release g_tab / out writes
        atomicAdd((unsigned int*)&g_arrive, 1u);
        while ((int)g_arrive < nblk) __nanosleep(64);
        __threadfence();                     // acquire
    }
    __syncthreads();

    // ---------------- Phase 2: loss, 1 pixel per thread (grid-stride) -------
    const int nthreads = nblk * NTHR;
    float acc = 0.0f;

    for (int px = blockIdx.x * NTHR + threadIdx.x; px < 262144; px += nthreads) {
        const int bb    = px >> 16;
        const int n     = px & 65535;
        const int base0 = bb * 131072 + n;

        const float t0 = target[base0];
        const float t1 = target[base0 + 65536];
        const float i0 = input[base0];
        const float i1 = input[base0 + 65536];

        // clamp-free cell: t in [-1,1] -> [0, 63.999]; slop covered by pad
        const int ix = (int)((t0 + 1.0f) * 31.9995f);
        const int iy = (int)((t1 + 1.0f) * 31.9995f);
        const int cc = (iy << 6) | ix;

        const float4* tab = &g_tab[cc * 8];
        const float4 c0 = tab[0];
        const float4 c1 = tab[1];
        const float4 c2v = tab[2];
        const float4 c3 = tab[3];

        const bool ovf4 = (c0.z < 0.0f);
        float bestSc = fmaf(c0.x, t0, fmaf(c0.y, t1, fabsf(c0.z)));
        float bestW  = c0.w;

        float sc;
        sc = fmaf(c1.x, t0, fmaf(c1.y, t1, c1.z));
        if (sc < bestSc) { bestSc = sc; bestW = c1.w; }
        sc = fmaf(c2v.x, t0, fmaf(c2v.y, t1, c2v.z));
        if (sc < bestSc) { bestSc = sc; bestW = c2v.w; }
        sc = fmaf(c3.x, t0, fmaf(c3.y, t1, c3.z));
        if (sc < bestSc) { bestSc = sc; bestW = c3.w; }

        if (ovf4) {
            const float4 c4 = tab[4];
            const float4 c5 = tab[5];
            const float4 c6 = tab[6];
            const float4 c7 = tab[7];
            const bool ovf8 = (c4.z < 0.0f);

            sc = fmaf(c4.x, t0, fmaf(c4.y, t1, fabsf(c4.z)));
            if (sc < bestSc) { bestSc = sc; bestW = c4.w; }
            sc = fmaf(c5.x, t0, fmaf(c5.y, t1, c5.z));
            if (sc < bestSc) { bestSc = sc; bestW = c5.w; }
            sc = fmaf(c6.x, t0, fmaf(c6.y, t1, c6.z));
            if (sc < bestSc) { bestSc = sc; bestW = c6.w; }
            sc = fmaf(c7.x, t0, fmaf(c7.y, t1, c7.z));
            if (sc < bestSc) { bestSc = sc; bestW = c7.w; }

            if (ovf8) {
                // exact full scan (vanishingly rare): consistent formula per px
                bestSc = 1e30f;
                int bestIdx = 0;
                for (int bi = 0; bi < Q; bi++) {
                    const float2 g = gamut[bi];
                    const float s2 = fmaf(g.x, g.x, fmaf(g.y, g.y, 16.0f));
                    const float v  = fmaf(-2.0f * g.x, t0,
                                     fmaf(-2.0f * g.y, t1, s2));
                    if (v < bestSc) { bestSc = v; bestIdx = bi; }
                }
                bestW = prior[bestIdx];
            }
        }

        const float d0 = i0 - t0;
        const float d1 = i1 - t1;
        acc += bestW * fmaf(d0, d0, d1 * d1);
    }

    acc *= 0.25f;   // mean over batch b = 4

    #pragma unroll
    for (int off = 16; off; off >>= 1)
        acc += __shfl_xor_sync(0xFFFFFFFFu, acc, off);

    if (lane == 0) ws[warp] = acc;
    __syncthreads();
    if (threadIdx.x < 8) {
        float v = ws[threadIdx.x];
        #pragma unroll
        for (int off = 4; off; off >>= 1)
            v += __shfl_xor_sync(0xFFu, v, off);
        if (threadIdx.x == 0) atomicAdd(out, v);
    }

    // ---------------- reset barrier for next graph replay -------------------
    if (threadIdx.x == 0) {
        __threadfence();
        if (atomicAdd(&g_done, 1u) == (unsigned)(nblk - 1)) {
            g_arrive = 0;
            g_done   = 0;
            __threadfence();
        }
    }
}

// ---------------------------------------------------------------------------
extern "C" void kernel_launch(void* const* d_in, const int* in_sizes, int n_in,
                              void* d_out, int out_size)
{
    const float*  input  = (const float*)d_in[0];
    const float*  target = (const float*)d_in[1];
    const float2* gamut  = (const float2*)d_in[2];   // [Q,2]
    const float*  prior  = (const float*)d_in[3];    // [Q]
    float* out = (float*)d_out;
    const int Q = in_sizes[3];                        // 313

    // Grid sized so ALL blocks are co-resident (grid barrier is safe by
    // construction). Deterministic for a fixed device + binary.
    int dev = 0;
    cudaGetDevice(&dev);
    int sms = 148;
    cudaDeviceGetAttribute(&sms, cudaDevAttrMultiProcessorCount, dev);
    int maxb = 1;
    cudaOccupancyMaxActiveBlocksPerMultiprocessor(&maxb, fused_loss_kernel,
                                                  NTHR, 0);
    int blocks = sms * maxb;
    if (blocks > 1024) blocks = 1024;   // 262144 px / 256 thr = 1024 max useful
    if (blocks < 1)    blocks = 1;

    fused_loss_kernel<<<blocks, NTHR>>>(input, target, gamut, prior, out,
                                        Q, blocks);
}

// round 6
// speedup vs baseline: 1.9239x; 1.9239x over previous
#include <cuda_runtime.h>
#include <stdint.h>

// ============================================================================
// Fused colorization L2Loss (build + grid barrier + loss in ONE kernel).
//   loss = mean_b sum_{c,h,w} (in-tgt)^2 * prior[argmin_q d2(tgt_px, gamut[q])]
//
// Build: 512 blk x 8 warps = 4096 warps, ONE warp per 64x64 cell. Candidate
//   set = bins with d(center,bin) <= dmin(center)+diag (provable NN superset).
//   Materializes 4 candidates per cell as float4(-2gx,-2gy,|g|^2+16,prior),
//   dup-padded, ascending index. slot0.z sign-flag => overflow (u16 list path).
// Barrier: atomicAdd arrive + volatile poll (512 blocks co-resident: ~45 regs,
//   ~7KB smem -> 4 blk/SM capacity >= 3.46 needed).
// Loss: 2 px/thread (512x256x2 = 262144), float2 loads, 4 parallel LDG.128
//   candidate evals, exact strict-< argmin (ascending index = argmin tiebreak).
// ============================================================================

#define LGRID 64
#define NCELL (LGRID * LGRID)
#define CAP   32
#define MAXQ  320          // >= Q=313, exactly 10 warp-iterations
#define NBLK  512
#define NTHR  256

__device__ float4          g_quad[NCELL * 4];   // 256 KB materialized table
__device__ unsigned short  g_cand[NCELL * CAP]; // overflow lists (rare)
__device__ unsigned int    g_cnt[NCELL];
__device__ volatile unsigned int g_arrive;      // zero-init; reset at end
__device__ unsigned int          g_done;

__global__ void __launch_bounds__(NTHR) fused_loss_kernel(
    const float*  __restrict__ input,
    const float*  __restrict__ target,
    const float2* __restrict__ gamut,
    const float*  __restrict__ prior,
    float*        __restrict__ out,
    int Q)
{
    __shared__ float4 sf[MAXQ];                 // (-2gx, -2gy, |g|^2+16, prior)
    __shared__ unsigned short scand[8][CAP];
    __shared__ float ws[8];

    for (int i = threadIdx.x; i < Q; i += NTHR) {
        const float2 g = gamut[i];
        sf[i] = make_float4(-2.0f * g.x, -2.0f * g.y,
                            fmaf(g.x, g.x, fmaf(g.y, g.y, 16.0f)),
                            prior[i]);
    }
    __syncthreads();

    const int warp = threadIdx.x >> 5;
    const int lane = threadIdx.x & 31;

    // ---------------- Phase 1: build (one warp per cell) --------------------
    {
        const int cell = blockIdx.x * 8 + warp;      // 512*8 = 4096 exactly

        const int ix = cell & (LGRID - 1);
        const int iy = cell >> 6;
        const float cellw = 2.0f / (float)LGRID;
        const float cx = -1.0f + ((float)ix + 0.5f) * cellw;
        const float cy = -1.0f + ((float)iy + 0.5f) * cellw;
        const float c2 = fmaf(cx, cx, cy * cy);
        const float diag = 0.04450f;                 // 0.044194 + FP pad

        // score = d2 + 16 - c2, identical fma form to the loss phase
        float scv[MAXQ / 32];
        float smin = 1e30f;
        #pragma unroll
        for (int j = 0; j < MAXQ / 32; j++) {
            const int b = (j << 5) + lane;
            float sc = 1e30f;
            if (b < Q) {
                const float4 g = sf[b];
                sc = fmaf(g.x, cx, fmaf(g.y, cy, g.z));
            }
            scv[j] = sc;
            smin = fminf(smin, sc);
        }
        #pragma unroll
        for (int off = 16; off; off >>= 1)
            smin = fminf(smin, __shfl_xor_sync(0xFFFFFFFFu, smin, off));

        const float d2min = fmaxf(smin - 16.0f + c2, 0.0f);
        const float s     = sqrtf(d2min) + diag;
        const float thr   = fmaf(s, s, 16.0f - c2) + 2e-5f;

        int base = 0;
        #pragma unroll
        for (int j = 0; j < MAXQ / 32; j++) {
            const bool take = (scv[j] <= thr);
            const unsigned m = __ballot_sync(0xFFFFFFFFu, take);
            if (take) {
                const int pos = base + __popc(m & ((1u << lane) - 1u));
                if (pos < CAP)
                    scand[warp][pos] = (unsigned short)((j << 5) + lane);
            }
            base += __popc(m);
        }
        __syncwarp();

        if (base > 4) {                              // rare overflow list
            const int nw = min(base, CAP);
            for (int j = lane; j < nw; j += 32)
                g_cand[cell * CAP + j] = scand[warp][j];
            if (lane == 0) g_cnt[cell] = (unsigned)base;
        }
        if (lane < 4) {                              // materialize 4 slots
            const int sel = (lane < base) ? lane : 0;
            float4 v = sf[scand[warp][sel]];
            if (lane == 0 && base > 4) v.z = -v.z;   // overflow flag
            g_quad[cell * 4 + lane] = v;
        }
        __syncwarp();
    }

    if (blockIdx.x == 0 && threadIdx.x == 0) out[0] = 0.0f;

    // ---------------- Grid barrier -----------------------------------------
    __syncthreads();
    if (threadIdx.x == 0) {
        __threadfence();                             // release g_quad / out
        atomicAdd((unsigned int*)&g_arrive, 1u);
        while (g_arrive < NBLK) __nanosleep(64);
        __threadfence();                             // acquire
    }
    __syncthreads();

    // ---------------- Phase 2: loss, 2 consecutive pixels per thread --------
    const int tid   = blockIdx.x * NTHR + threadIdx.x;  // 0..131071
    const int q     = tid << 1;
    const int bb    = q >> 16;
    const int n     = q & 65535;
    const int base0 = bb * 131072 + n;

    const float2 tv0 = *(const float2*)(target + base0);
    const float2 tv1 = *(const float2*)(target + base0 + 65536);
    const float2 iv0 = *(const float2*)(input  + base0);
    const float2 iv1 = *(const float2*)(input  + base0 + 65536);

    const float ta[2] = {tv0.x, tv0.y};
    const float tb[2] = {tv1.x, tv1.y};
    const float ia[2] = {iv0.x, iv0.y};
    const float ib[2] = {iv1.x, iv1.y};

    float acc = 0.0f;

    #pragma unroll
    for (int k = 0; k < 2; k++) {
        const float t0 = ta[k], t1 = tb[k];
        // clamp-free cell: t in [-1,1] -> [0, 63.999]; slop inside pad
        const int ix = (int)((t0 + 1.0f) * 31.9995f);
        const int iy = (int)((t1 + 1.0f) * 31.9995f);
        const int cc = (iy << 6) | ix;

        const float4* qp = &g_quad[cc * 4];
        const float4 q0 = qp[0];
        const float4 q1 = qp[1];
        const float4 q2 = qp[2];
        const float4 q3 = qp[3];

        const bool flag = (q0.z < 0.0f);
        float bestSc = fmaf(q0.x, t0, fmaf(q0.y, t1, fabsf(q0.z)));
        float bestW  = q0.w;

        float sc;
        sc = fmaf(q1.x, t0, fmaf(q1.y, t1, q1.z));
        if (sc < bestSc) { bestSc = sc; bestW = q1.w; }
        sc = fmaf(q2.x, t0, fmaf(q2.y, t1, q2.z));
        if (sc < bestSc) { bestSc = sc; bestW = q2.w; }
        sc = fmaf(q3.x, t0, fmaf(q3.y, t1, q3.z));
        if (sc < bestSc) { bestSc = sc; bestW = q3.w; }

        if (flag) {                                  // rare: exact re-scan
            bestSc = 1e30f;
            int bestIdx = 0;
            const unsigned cnt = g_cnt[cc];
            if (cnt <= CAP) {
                const unsigned short* cl = &g_cand[cc * CAP];
                for (unsigned j = 0; j < cnt; j++) {
                    const int bi = (int)cl[j];
                    const float2 g = gamut[bi];
                    const float cz = fmaf(g.x, g.x, fmaf(g.y, g.y, 16.0f));
                    const float v  = fmaf(-2.0f * g.x, t0,
                                     fmaf(-2.0f * g.y, t1, cz));
                    if (v < bestSc) { bestSc = v; bestIdx = bi; }
                }
            } else {
                for (int bi = 0; bi < Q; bi++) {
                    const float2 g = gamut[bi];
                    const float cz = fmaf(g.x, g.x, fmaf(g.y, g.y, 16.0f));
                    const float v  = fmaf(-2.0f * g.x, t0,
                                     fmaf(-2.0f * g.y, t1, cz));
                    if (v < bestSc) { bestSc = v; bestIdx = bi; }
                }
            }
            bestW = prior[bestIdx];
        }

        const float d0 = ia[k] - t0;
        const float d1 = ib[k] - t1;
        acc += bestW * fmaf(d0, d0, d1 * d1);
    }

    acc *= 0.25f;   // mean over batch b = 4

    #pragma unroll
    for (int off = 16; off; off >>= 1)
        acc += __shfl_xor_sync(0xFFFFFFFFu, acc, off);

    if (lane == 0) ws[warp] = acc;
    __syncthreads();
    if (threadIdx.x < 8) {
        float v = ws[threadIdx.x];
        #pragma unroll
        for (int off = 4; off; off >>= 1)
            v += __shfl_xor_sync(0xFFu, v, off);
        if (threadIdx.x == 0) atomicAdd(out, v);
    }

    // ---------------- reset barrier for next graph replay -------------------
    if (threadIdx.x == 0) {
        __threadfence();
        if (atomicAdd(&g_done, 1u) == NBLK - 1) {
            g_arrive = 0;
            g_done   = 0;
            __threadfence();
        }
    }
}

// ---------------------------------------------------------------------------
extern "C" void kernel_launch(void* const* d_in, const int* in_sizes, int n_in,
                              void* d_out, int out_size)
{
    const float*  input  = (const float*)d_in[0];
    const float*  target = (const float*)d_in[1];
    const float2* gamut  = (const float2*)d_in[2];   // [Q,2]
    const float*  prior  = (const float*)d_in[3];    // [Q]
    float* out = (float*)d_out;
    const int Q = in_sizes[3];                        // 313

    fused_loss_kernel<<<NBLK, NTHR>>>(input, target, gamut, prior, out, Q);
}